// round 4
// baseline (speedup 1.0000x reference)
#include <cuda_runtime.h>

// ---- problem constants ----
#define Bq   8
#define Sq   1024
#define Dq   1024
#define Hq   16
#define DHq  64
#define Rq   128
#define KCq  16
#define KEq  8
#define D3q  (3*Dq)

// ---- scratch (static device allocations; no cudaMalloc anywhere) ----
__device__ float g_Wc  [(size_t)Bq*Dq*Rq];        //  4M  [B][D][R]
__device__ float g_h   [(size_t)Bq*Sq*Rq];        //  4M  [B][S][R]
__device__ float g_Wqkv[(size_t)Bq*Rq*D3q];       // 12M  [B][R][3D] (Q|K|V cols)
__device__ float g_QKV [(size_t)Bq*Sq*D3q];       // 96M  [B][S][3D]
__device__ float g_att [(size_t)Bq*Sq*Dq];        // 32M  [B][S][D]

// ============================================================
// 1) Wc[b,d,r] = sum_k cw[b,k] * neurons[cidx[b,k], d, r]
// ============================================================
__global__ __launch_bounds__(256) void build_wc(
    const float* __restrict__ cw, const int* __restrict__ ci,
    const float* __restrict__ neurons, float* __restrict__ out)
{
    const int b = blockIdx.y;
    __shared__ float sw[KCq];
    __shared__ int   si[KCq];
    if (threadIdx.x < KCq) {
        sw[threadIdx.x] = cw[b*KCq + threadIdx.x];
        si[threadIdx.x] = ci[b*KCq + threadIdx.x];
    }
    __syncthreads();
    const int i = blockIdx.x*blockDim.x + threadIdx.x;   // float4 index over D*R
    float4 acc = make_float4(0.f,0.f,0.f,0.f);
    #pragma unroll
    for (int k = 0; k < KCq; k++) {
        const float4 v = ((const float4*)(neurons + (long long)si[k]*Dq*Rq))[i];
        const float w = sw[k];
        acc.x += w*v.x; acc.y += w*v.y; acc.z += w*v.z; acc.w += w*v.w;
    }
    ((float4*)(out + (long long)b*Dq*Rq))[i] = acc;
}

// ============================================================
// 2) Wqkv[b, r, m*D + d] = sum_k w_m[b,k] * pool[idx_m[b,k], r, d]
// ============================================================
__global__ __launch_bounds__(256) void build_wqkv(
    const float* __restrict__ wQ, const float* __restrict__ wK, const float* __restrict__ wV,
    const int* __restrict__ iQ, const int* __restrict__ iK, const int* __restrict__ iV,
    const float* __restrict__ pool, float* __restrict__ out)
{
    const int m = blockIdx.y, b = blockIdx.z;
    const float* w = (m==0) ? wQ : (m==1) ? wK : wV;
    const int*  id = (m==0) ? iQ : (m==1) ? iK : iV;
    __shared__ float sw[KEq];
    __shared__ int   si[KEq];
    if (threadIdx.x < KEq) {
        sw[threadIdx.x] = w[b*KEq + threadIdx.x];
        si[threadIdx.x] = id[b*KEq + threadIdx.x];
    }
    __syncthreads();
    const int i = blockIdx.x*blockDim.x + threadIdx.x;   // float4 index over R*D
    float4 acc = make_float4(0.f,0.f,0.f,0.f);
    #pragma unroll
    for (int k = 0; k < KEq; k++) {
        const float4 v = ((const float4*)(pool + (long long)si[k]*Rq*Dq))[i];
        const float wk = sw[k];
        acc.x += wk*v.x; acc.y += wk*v.y; acc.z += wk*v.z; acc.w += wk*v.w;
    }
    const int e = i*4;
    const int r = e / Dq, d = e % Dq;
    *(float4*)(out + (long long)b*Rq*D3q + (long long)r*D3q + m*Dq + d) = acc;
}

// ============================================================
// Generic batched tiled SGEMM:  C = A[M,K] * B[K,N]   (TRB: B stored [N,K])
// ============================================================
template<int BM,int BN,int BK,int TM,int TN,bool TRB>
__global__ __launch_bounds__((BM/TM)*(BN/TN)) void sgemm_kernel(
    const float* __restrict__ A, const float* __restrict__ Bm, float* __restrict__ C,
    int M, int N, int K, long long sA, long long sB, long long sC)
{
    constexpr int THREADS = (BM/TM)*(BN/TN);
    __shared__ float As[BK][BM+4];   // k-major (transposed), padded
    __shared__ float Bs[BK][BN];
    const int bz = blockIdx.z;
    A += bz*sA; Bm += bz*sB; C += bz*sC;
    const int bm = blockIdx.y*BM, bn = blockIdx.x*BN;
    const int tid = threadIdx.x;
    const int tx = tid % (BN/TN);
    const int ty = tid / (BN/TN);

    float acc[TM][TN];
    #pragma unroll
    for (int i=0;i<TM;i++)
        #pragma unroll
        for (int j=0;j<TN;j++) acc[i][j]=0.f;

    for (int k0 = 0; k0 < K; k0 += BK) {
        constexpr int AL = BM*BK/(THREADS*4);
        #pragma unroll
        for (int l=0;l<AL;l++) {
            const int idx = (tid + l*THREADS)*4;
            const int r = idx / BK, c = idx % BK;
            const float4 v = *(const float4*)(A + (long long)(bm+r)*K + k0 + c);
            As[c+0][r]=v.x; As[c+1][r]=v.y; As[c+2][r]=v.z; As[c+3][r]=v.w;
        }
        constexpr int BL = BK*BN/(THREADS*4);
        if (!TRB) {
            #pragma unroll
            for (int l=0;l<BL;l++) {
                const int idx = (tid + l*THREADS)*4;
                const int r = idx / BN, c = idx % BN;
                *(float4*)&Bs[r][c] = *(const float4*)(Bm + (long long)(k0+r)*N + bn + c);
            }
        } else {
            #pragma unroll
            for (int l=0;l<BL;l++) {
                const int idx = (tid + l*THREADS)*4;
                const int n = idx / BK, c = idx % BK;
                const float4 v = *(const float4*)(Bm + (long long)(bn+n)*K + k0 + c);
                Bs[c+0][n]=v.x; Bs[c+1][n]=v.y; Bs[c+2][n]=v.z; Bs[c+3][n]=v.w;
            }
        }
        __syncthreads();
        #pragma unroll
        for (int kk=0;kk<BK;kk++) {
            float ar[TM], br[TN];
            #pragma unroll
            for (int i=0;i<TM;i++) ar[i]=As[kk][ty*TM+i];
            #pragma unroll
            for (int j=0;j<TN;j++) br[j]=Bs[kk][tx*TN+j];
            #pragma unroll
            for (int i=0;i<TM;i++)
                #pragma unroll
                for (int j=0;j<TN;j++) acc[i][j] += ar[i]*br[j];
        }
        __syncthreads();
    }
    #pragma unroll
    for (int i=0;i<TM;i++) {
        #pragma unroll
        for (int j=0;j<TN;j+=4) {
            float4 v = make_float4(acc[i][j],acc[i][j+1],acc[i][j+2],acc[i][j+3]);
            *(float4*)(C + (long long)(bm+ty*TM+i)*N + bn + tx*TN + j) = v;
        }
    }
}

// ============================================================
// Causal flash attention over g_QKV, writes g_att [B,S,D].
// 64q x 64k tiles, 256 threads (16x16 of 4x4 fragments), DH=64.
// Q and K staged k-major in smem; P overlays K's buffer.
// ============================================================
#define ASTR 68
#define ATTN_SMEM (3*64*ASTR*4)

__global__ __launch_bounds__(256) void flash_attn(
    const float* __restrict__ QKV, float* __restrict__ Oatt)
{
    extern __shared__ float sm[];
    float* QT = sm;                 // [64 kk][ASTR r]
    float* KT = sm + 64*ASTR;       // [64 kk][ASTR c]  — reused as PT[c][r]
    float* Vs = sm + 2*64*ASTR;     // [64 c ][ASTR d]
    const int qb = blockIdx.x, h = blockIdx.y, b = blockIdx.z;
    const int tid = threadIdx.x;
    const int tx = tid & 15, ty = tid >> 4;
    const float scale = 0.125f;     // 1/sqrt(64)
    const long long baseQ = (long long)b*Sq*D3q + (long long)h*DHq;
    const long long baseK = baseQ + Dq;
    const long long baseV = baseQ + 2*Dq;
    const int q0 = qb*64;

    // load Q tile transposed (coalesced float4 reads, scatter to k-major)
    #pragma unroll
    for (int l=0;l<4;l++) {
        const int t = tid + l*256;
        const int r = t >> 4;
        const int c4 = (t & 15) << 2;
        const float4 v = *(const float4*)(QKV + baseQ + (long long)(q0+r)*D3q + c4);
        QT[(c4+0)*ASTR + r]=v.x; QT[(c4+1)*ASTR + r]=v.y;
        QT[(c4+2)*ASTR + r]=v.z; QT[(c4+3)*ASTR + r]=v.w;
    }

    float m_i[4], l_i[4], acc[4][4];
    #pragma unroll
    for (int i=0;i<4;i++) {
        m_i[i] = -1e30f; l_i[i] = 0.f;
        #pragma unroll
        for (int j=0;j<4;j++) acc[i][j]=0.f;
    }

    for (int kb = 0; kb <= qb; kb++) {
        const int k0 = kb*64;
        __syncthreads();   // previous iter done reading KT/Vs (also orders QT stores)
        #pragma unroll
        for (int l=0;l<4;l++) {
            const int t = tid + l*256;
            const int r = t >> 4;
            const int c4 = (t & 15) << 2;
            const float4 v = *(const float4*)(QKV + baseK + (long long)(k0+r)*D3q + c4);
            KT[(c4+0)*ASTR + r]=v.x; KT[(c4+1)*ASTR + r]=v.y;
            KT[(c4+2)*ASTR + r]=v.z; KT[(c4+3)*ASTR + r]=v.w;
            const float4 u = *(const float4*)(QKV + baseV + (long long)(k0+r)*D3q + c4);
            *(float4*)&Vs[r*ASTR + c4] = u;
        }
        __syncthreads();

        // S = Q K^T (4x4 fragment per thread)
        float s[4][4];
        #pragma unroll
        for (int i=0;i<4;i++)
            #pragma unroll
            for (int j=0;j<4;j++) s[i][j]=0.f;
        #pragma unroll 4
        for (int kk=0;kk<64;kk++) {
            const float4 av = *(const float4*)&QT[kk*ASTR + ty*4];
            const float4 bv = *(const float4*)&KT[kk*ASTR + tx*4];
            const float a0=av.x,a1=av.y,a2=av.z,a3=av.w;
            const float b0=bv.x,b1=bv.y,b2=bv.z,b3=bv.w;
            s[0][0]+=a0*b0; s[0][1]+=a0*b1; s[0][2]+=a0*b2; s[0][3]+=a0*b3;
            s[1][0]+=a1*b0; s[1][1]+=a1*b1; s[1][2]+=a1*b2; s[1][3]+=a1*b3;
            s[2][0]+=a2*b0; s[2][1]+=a2*b1; s[2][2]+=a2*b2; s[2][3]+=a2*b3;
            s[3][0]+=a3*b0; s[3][1]+=a3*b1; s[3][2]+=a3*b2; s[3][3]+=a3*b3;
        }

        // scale + causal mask (diagonal tile only)
        const bool diag = (kb == qb);
        #pragma unroll
        for (int i=0;i<4;i++) {
            const int r = ty*4 + i;
            #pragma unroll
            for (int j=0;j<4;j++) {
                const int c = tx*4 + j;
                float v = s[i][j]*scale;
                if (diag && c > r) v = -1e30f;
                s[i][j] = v;
            }
        }

        // online softmax (row stats reduced over the 16 tx lanes)
        #pragma unroll
        for (int i=0;i<4;i++) {
            float rm = fmaxf(fmaxf(s[i][0],s[i][1]), fmaxf(s[i][2],s[i][3]));
            #pragma unroll
            for (int m=1;m<16;m<<=1) rm = fmaxf(rm, __shfl_xor_sync(0xffffffffu, rm, m));
            const float mnew = fmaxf(m_i[i], rm);
            const float f = __expf(m_i[i] - mnew);
            float rs = 0.f;
            #pragma unroll
            for (int j=0;j<4;j++) { const float p = __expf(s[i][j]-mnew); s[i][j]=p; rs += p; }
            #pragma unroll
            for (int m=1;m<16;m<<=1) rs += __shfl_xor_sync(0xffffffffu, rs, m);
            l_i[i] = l_i[i]*f + rs;
            m_i[i] = mnew;
            #pragma unroll
            for (int j=0;j<4;j++) acc[i][j] *= f;
        }

        __syncthreads();   // everyone done reading KT before overwrite with P
        #pragma unroll
        for (int i=0;i<4;i++)
            #pragma unroll
            for (int j=0;j<4;j++)
                KT[(tx*4+j)*ASTR + ty*4 + i] = s[i][j];   // PT[c][r]
        __syncthreads();

        // O += P V
        #pragma unroll 4
        for (int cc=0;cc<64;cc++) {
            const float4 av = *(const float4*)&KT[cc*ASTR + ty*4];
            const float4 bv = *(const float4*)&Vs[cc*ASTR + tx*4];
            const float a0=av.x,a1=av.y,a2=av.z,a3=av.w;
            const float b0=bv.x,b1=bv.y,b2=bv.z,b3=bv.w;
            acc[0][0]+=a0*b0; acc[0][1]+=a0*b1; acc[0][2]+=a0*b2; acc[0][3]+=a0*b3;
            acc[1][0]+=a1*b0; acc[1][1]+=a1*b1; acc[1][2]+=a1*b2; acc[1][3]+=a1*b3;
            acc[2][0]+=a2*b0; acc[2][1]+=a2*b1; acc[2][2]+=a2*b2; acc[2][3]+=a2*b3;
            acc[3][0]+=a3*b0; acc[3][1]+=a3*b1; acc[3][2]+=a3*b2; acc[3][3]+=a3*b3;
        }
    }

    // epilogue: normalize + write [B,S,D] with d = h*64 + dh
    #pragma unroll
    for (int i=0;i<4;i++) {
        const float inv = 1.0f / l_i[i];
        const int r = q0 + ty*4 + i;
        const float4 v = make_float4(acc[i][0]*inv, acc[i][1]*inv, acc[i][2]*inv, acc[i][3]*inv);
        *(float4*)(Oatt + (long long)b*Sq*Dq + (long long)r*Dq + h*DHq + tx*4) = v;
    }
}

// ============================================================
// launch
// ============================================================
extern "C" void kernel_launch(void* const* d_in, const int* in_sizes, int n_in,
                              void* d_out, int out_size)
{
    const float* x       = (const float*)d_in[0];
    const float* cw      = (const float*)d_in[1];
    const int*   ci      = (const int*)  d_in[2];
    const float* wQ      = (const float*)d_in[3];
    const int*   iQ      = (const int*)  d_in[4];
    const float* wK      = (const float*)d_in[5];
    const int*   iK      = (const int*)  d_in[6];
    const float* wV      = (const float*)d_in[7];
    const int*   iV      = (const int*)  d_in[8];
    const float* neurons = (const float*)d_in[9];
    const float* pool    = (const float*)d_in[10];
    const float* WO      = (const float*)d_in[11];
    float* out = (float*)d_out;

    float *pWc, *ph, *pWqkv, *pQKV, *patt;
    cudaGetSymbolAddress((void**)&pWc,   g_Wc);
    cudaGetSymbolAddress((void**)&ph,    g_h);
    cudaGetSymbolAddress((void**)&pWqkv, g_Wqkv);
    cudaGetSymbolAddress((void**)&pQKV,  g_QKV);
    cudaGetSymbolAddress((void**)&patt,  g_att);

    // 1) per-batch compress weights  Wc[B,D,R]
    build_wc<<<dim3(Dq*Rq/4/256, Bq), 256>>>(cw, ci, neurons, pWc);

    // 2) per-batch expand weights, Q|K|V concatenated  Wqkv[B,R,3D]
    build_wqkv<<<dim3(Rq*Dq/4/256, 3, Bq), 256>>>(wQ, wK, wV, iQ, iK, iV, pool, pWqkv);

    // 3) h = x @ Wc   (M=1024, N=128, K=1024, batch 8)
    sgemm_kernel<64,64,16,4,4,false><<<dim3(Rq/64, Sq/64, Bq), 256>>>(
        x, pWc, ph, Sq, Rq, Dq,
        (long long)Sq*Dq, (long long)Dq*Rq, (long long)Sq*Rq);

    // 4) QKV = h @ Wqkv   (M=1024, N=3072, K=128, batch 8)
    sgemm_kernel<128,128,16,8,8,false><<<dim3(D3q/128, Sq/128, Bq), 256>>>(
        ph, pWqkv, pQKV, Sq, D3q, Rq,
        (long long)Sq*Rq, (long long)Rq*D3q, (long long)Sq*D3q);

    // 5) causal flash attention -> g_att [B,S,D]
    cudaFuncSetAttribute(flash_attn, cudaFuncAttributeMaxDynamicSharedMemorySize, ATTN_SMEM);
    flash_attn<<<dim3(Sq/64, Hq, Bq), 256, ATTN_SMEM>>>(pQKV, patt);

    // 6) Y = att @ W_O^T   (M=8192, N=1024, K=1024, W_O stored [N,K])
    sgemm_kernel<128,128,16,8,8,true><<<dim3(Dq/128, (Bq*Sq)/128, 1), 256>>>(
        patt, WO, out, Bq*Sq, Dq, Dq, 0, 0, 0);
}

// round 9
// speedup vs baseline: 1.3641x; 1.3641x over previous
#include <cuda_runtime.h>
#include <cuda_bf16.h>
#include <cstdint>

// ---- problem constants ----
#define Bq   8
#define Sq   1024
#define Dq   1024
#define Hq   16
#define DHq  64
#define Rq   128
#define KCq  16
#define KEq  8
#define D3q  (3*Dq)

// ---- scratch (static device allocations; no cudaMalloc anywhere) ----
__device__ __nv_bfloat16 g_xhi [(size_t)Bq*Sq*Dq];
__device__ __nv_bfloat16 g_xlo [(size_t)Bq*Sq*Dq];
__device__ float         g_Wc  [(size_t)Bq*Dq*Rq];     // [B][D][R] fp32
__device__ __nv_bfloat16 g_WcThi[(size_t)Bq*Rq*Dq];    // [B][R][D]
__device__ __nv_bfloat16 g_WcTlo[(size_t)Bq*Rq*Dq];
__device__ __nv_bfloat16 g_hhi [(size_t)Bq*Sq*Rq];     // [B][S][R]
__device__ __nv_bfloat16 g_hlo [(size_t)Bq*Sq*Rq];
__device__ float         g_Wqkv[(size_t)Bq*Rq*D3q];    // [B][R][3D] fp32
__device__ __nv_bfloat16 g_WqThi[(size_t)Bq*D3q*Rq];   // [B][3D][R]
__device__ __nv_bfloat16 g_WqTlo[(size_t)Bq*D3q*Rq];
__device__ float         g_QKV [(size_t)Bq*Sq*D3q];    // [B][S][3D] fp32
__device__ __nv_bfloat16 g_atthi[(size_t)Bq*Sq*Dq];    // [B][S][D]
__device__ __nv_bfloat16 g_attlo[(size_t)Bq*Sq*Dq];
__device__ __nv_bfloat16 g_WOhi[(size_t)Dq*Dq];        // [N][K] natural
__device__ __nv_bfloat16 g_WOlo[(size_t)Dq*Dq];

// ============================================================
// helpers: mma.sync bf16 + cp.async (plain compute_103 features)
// ============================================================
__device__ __forceinline__ uint32_t s2u(const void* p) {
    uint32_t a;
    asm("{ .reg .u64 t; cvta.to.shared.u64 t, %1; cvt.u32.u64 %0, t; }" : "=r"(a) : "l"(p));
    return a;
}
__device__ __forceinline__ void mma16816(float* d, const uint32_t* a, const uint32_t* b) {
    asm volatile(
        "mma.sync.aligned.m16n8k16.row.col.f32.bf16.bf16.f32 "
        "{%0,%1,%2,%3}, {%4,%5,%6,%7}, {%8,%9}, {%0,%1,%2,%3};"
        : "+f"(d[0]), "+f"(d[1]), "+f"(d[2]), "+f"(d[3])
        : "r"(a[0]), "r"(a[1]), "r"(a[2]), "r"(a[3]), "r"(b[0]), "r"(b[1]));
}
__device__ __forceinline__ void cp16(uint32_t saddr, const void* g) {
    asm volatile("cp.async.cg.shared.global [%0], [%1], 16;" :: "r"(saddr), "l"(g));
}
__device__ __forceinline__ void cpcommit() { asm volatile("cp.async.commit_group;"); }
template<int N> __device__ __forceinline__ void cpwait() {
    asm volatile("cp.async.wait_group %0;" :: "n"(N));
    __syncthreads();
}

// ============================================================
// fp32 -> (hi, lo) bf16 split, elementwise (float4 granularity)
// ============================================================
__global__ __launch_bounds__(256) void split_fp32(
    const float4* __restrict__ in, __nv_bfloat16* __restrict__ hi, __nv_bfloat16* __restrict__ lo)
{
    const long long i = (long long)blockIdx.x * 256 + threadIdx.x;
    const float4 v = in[i];
    __nv_bfloat16 h0 = __float2bfloat16(v.x), h1 = __float2bfloat16(v.y);
    __nv_bfloat16 h2 = __float2bfloat16(v.z), h3 = __float2bfloat16(v.w);
    __nv_bfloat162 ha; ha.x = h0; ha.y = h1;
    __nv_bfloat162 hb; hb.x = h2; hb.y = h3;
    __nv_bfloat162 la; la.x = __float2bfloat16(v.x - __bfloat162float(h0));
    la.y = __float2bfloat16(v.y - __bfloat162float(h1));
    __nv_bfloat162 lb; lb.x = __float2bfloat16(v.z - __bfloat162float(h2));
    lb.y = __float2bfloat16(v.w - __bfloat162float(h3));
    *(__nv_bfloat162*)(hi + i*4)     = ha;
    *(__nv_bfloat162*)(hi + i*4 + 2) = hb;
    *(__nv_bfloat162*)(lo + i*4)     = la;
    *(__nv_bfloat162*)(lo + i*4 + 2) = lb;
}

// ============================================================
// fp32 [Rr][Cc] -> bf16 hi/lo [Cc][Rr]  (transpose + split), batched
// ============================================================
__global__ __launch_bounds__(256) void transpose_split(
    const float* __restrict__ in, __nv_bfloat16* __restrict__ ohi, __nv_bfloat16* __restrict__ olo,
    int Rr, int Cc, long long sIn, long long sOut)
{
    __shared__ float t[32][33];
    in  += (long long)blockIdx.z * sIn;
    ohi += (long long)blockIdx.z * sOut;
    olo += (long long)blockIdx.z * sOut;
    const int x  = blockIdx.x * 32 + threadIdx.x;
    const int y0 = blockIdx.y * 32;
    #pragma unroll
    for (int j = threadIdx.y; j < 32; j += 8)
        t[j][threadIdx.x] = in[(long long)(y0 + j) * Cc + x];
    __syncthreads();
    const int r = y0 + threadIdx.x;
    #pragma unroll
    for (int j = threadIdx.y; j < 32; j += 8) {
        const int c = blockIdx.x * 32 + j;
        const float v = t[threadIdx.x][j];
        const __nv_bfloat16 hv = __float2bfloat16(v);
        ohi[(long long)c * Rr + r] = hv;
        olo[(long long)c * Rr + r] = __float2bfloat16(v - __bfloat162float(hv));
    }
}

// ============================================================
// gathers
// ============================================================
__global__ __launch_bounds__(256) void build_wc(
    const float* __restrict__ cw, const int* __restrict__ ci,
    const float* __restrict__ neurons, float* __restrict__ out)
{
    const int b = blockIdx.y;
    __shared__ float sw[KCq];
    __shared__ int   si[KCq];
    if (threadIdx.x < KCq) {
        sw[threadIdx.x] = cw[b*KCq + threadIdx.x];
        si[threadIdx.x] = ci[b*KCq + threadIdx.x];
    }
    __syncthreads();
    const int i = blockIdx.x*blockDim.x + threadIdx.x;
    float4 acc = make_float4(0.f,0.f,0.f,0.f);
    #pragma unroll
    for (int k = 0; k < KCq; k++) {
        const float4 v = ((const float4*)(neurons + (long long)si[k]*Dq*Rq))[i];
        const float w = sw[k];
        acc.x += w*v.x; acc.y += w*v.y; acc.z += w*v.z; acc.w += w*v.w;
    }
    ((float4*)(out + (long long)b*Dq*Rq))[i] = acc;
}

__global__ __launch_bounds__(256) void build_wqkv(
    const float* __restrict__ wQ, const float* __restrict__ wK, const float* __restrict__ wV,
    const int* __restrict__ iQ, const int* __restrict__ iK, const int* __restrict__ iV,
    const float* __restrict__ pool, float* __restrict__ out)
{
    const int m = blockIdx.y, b = blockIdx.z;
    const float* w = (m==0) ? wQ : (m==1) ? wK : wV;
    const int*  id = (m==0) ? iQ : (m==1) ? iK : iV;
    __shared__ float sw[KEq];
    __shared__ int   si[KEq];
    if (threadIdx.x < KEq) {
        sw[threadIdx.x] = w[b*KEq + threadIdx.x];
        si[threadIdx.x] = id[b*KEq + threadIdx.x];
    }
    __syncthreads();
    const int i = blockIdx.x*blockDim.x + threadIdx.x;
    float4 acc = make_float4(0.f,0.f,0.f,0.f);
    #pragma unroll
    for (int k = 0; k < KEq; k++) {
        const float4 v = ((const float4*)(pool + (long long)si[k]*Rq*Dq))[i];
        const float wk = sw[k];
        acc.x += wk*v.x; acc.y += wk*v.y; acc.z += wk*v.z; acc.w += wk*v.w;
    }
    const int e = i*4;
    const int r = e / Dq, d = e % Dq;
    *(float4*)(out + (long long)b*Rq*D3q + (long long)r*D3q + m*Dq + d) = acc;
}

// ============================================================
// HMMA split-bf16 GEMM:  C[M,N] = sum_k A[m,k]*B[n,k]
//   A hi/lo bf16 [M,K] (row stride lda); B hi/lo bf16 [N,K] (row stride ldb)
//   fp32 accum via mma.sync m16n8k16: D += Ah*Bh + Ah*Bl + Al*Bh
// CTA 128x128, 8 warps (2x4), warp tile 64x32, BK=32, cp.async double buffer.
// OUTM=0: fp32 C.  OUTM=1: split hi/lo bf16 C.
// ============================================================
#define GPAD 40                           // padded row length (elements)
#define GMAT (128*GPAD*2)                 // 10240 B per matrix
#define GSTG (4*GMAT)                     // 40960 B per stage
#define GSMEM (2*GSTG)                    // 81920 B

template<int OUTM>
__global__ __launch_bounds__(256) void gemm_hmma3(
    const __nv_bfloat16* __restrict__ Ahi, const __nv_bfloat16* __restrict__ Alo,
    const __nv_bfloat16* __restrict__ Bhi, const __nv_bfloat16* __restrict__ Blo,
    float* __restrict__ Cf, __nv_bfloat16* __restrict__ Chi, __nv_bfloat16* __restrict__ Clo,
    int lda, int ldb, int ldc, int K,
    long long zA, long long zB, long long zC)
{
    extern __shared__ char smem[];
    const uint32_t sb = s2u(smem);
    const int tid = threadIdx.x;
    const int wid = tid >> 5, lane = tid & 31;
    const int wm = wid >> 2, wn = wid & 3;
    const int mrow = lane >> 2;          // 0..7
    const int kcol = (lane & 3) * 2;     // 0,2,4,6
    const long long z = blockIdx.z;
    Ahi += z*zA; Alo += z*zA; Bhi += z*zB; Blo += z*zB;
    const int bm = blockIdx.y*128, bn = blockIdx.x*128;

    float acc[4][4][4];
    #pragma unroll
    for (int i=0;i<4;i++)
        #pragma unroll
        for (int j=0;j<4;j++)
            #pragma unroll
            for (int q=0;q<4;q++) acc[i][j][q]=0.f;

    const int nchunk = K / 32;

    // async stage loader: 512 16B-chunks per matrix, 2 per thread
    auto load_stage = [&](int buf, int k0) {
        const uint32_t s0 = sb + buf*GSTG;
        #pragma unroll
        for (int l = 0; l < 2; ++l) {
            const int ch = tid + l*256;
            const int row = ch >> 2, cc = ch & 3;
            const uint32_t so = (uint32_t)(row*(GPAD*2) + cc*16);
            const long long ga = (long long)(bm + row)*lda + k0 + cc*8;
            const long long gb = (long long)(bn + row)*ldb + k0 + cc*8;
            cp16(s0 +          so, Ahi + ga);
            cp16(s0 + GMAT   + so, Alo + ga);
            cp16(s0 + 2*GMAT + so, Bhi + gb);
            cp16(s0 + 3*GMAT + so, Blo + gb);
        }
    };

    load_stage(0, 0);
    cpcommit();

    for (int c = 0; c < nchunk; ++c) {
        if (c + 1 < nchunk) { load_stage((c+1)&1, (c+1)*32); cpcommit(); cpwait<1>(); }
        else                { cpcommit(); cpwait<0>(); }

        const char* st = smem + (c&1)*GSTG;
        const __nv_bfloat16* sAh = (const __nv_bfloat16*)(st);
        const __nv_bfloat16* sAl = (const __nv_bfloat16*)(st + GMAT);
        const __nv_bfloat16* sBh = (const __nv_bfloat16*)(st + 2*GMAT);
        const __nv_bfloat16* sBl = (const __nv_bfloat16*)(st + 3*GMAT);

        #pragma unroll
        for (int ks = 0; ks < 32; ks += 16) {
            uint32_t ah[4][4], al[4][4], bh[4][2], bl[4][2];
            #pragma unroll
            for (int i = 0; i < 4; ++i) {
                const int r0 = wm*64 + i*16 + mrow;
                ah[i][0] = *(const uint32_t*)&sAh[ r0      *GPAD + ks + kcol];
                ah[i][1] = *(const uint32_t*)&sAh[(r0 + 8) *GPAD + ks + kcol];
                ah[i][2] = *(const uint32_t*)&sAh[ r0      *GPAD + ks + kcol + 8];
                ah[i][3] = *(const uint32_t*)&sAh[(r0 + 8) *GPAD + ks + kcol + 8];
                al[i][0] = *(const uint32_t*)&sAl[ r0      *GPAD + ks + kcol];
                al[i][1] = *(const uint32_t*)&sAl[(r0 + 8) *GPAD + ks + kcol];
                al[i][2] = *(const uint32_t*)&sAl[ r0      *GPAD + ks + kcol + 8];
                al[i][3] = *(const uint32_t*)&sAl[(r0 + 8) *GPAD + ks + kcol + 8];
            }
            #pragma unroll
            for (int j = 0; j < 4; ++j) {
                const int n0 = wn*32 + j*8 + mrow;
                bh[j][0] = *(const uint32_t*)&sBh[n0*GPAD + ks + kcol];
                bh[j][1] = *(const uint32_t*)&sBh[n0*GPAD + ks + kcol + 8];
                bl[j][0] = *(const uint32_t*)&sBl[n0*GPAD + ks + kcol];
                bl[j][1] = *(const uint32_t*)&sBl[n0*GPAD + ks + kcol + 8];
            }
            #pragma unroll
            for (int i = 0; i < 4; ++i)
                #pragma unroll
                for (int j = 0; j < 4; ++j) {
                    mma16816(acc[i][j], ah[i], bh[j]);
                    mma16816(acc[i][j], ah[i], bl[j]);
                    mma16816(acc[i][j], al[i], bh[j]);
                }
        }
        __syncthreads();
    }

    // epilogue (direct register->gmem)
    #pragma unroll
    for (int i = 0; i < 4; ++i) {
        const int r0 = bm + wm*64 + i*16 + mrow;
        #pragma unroll
        for (int j = 0; j < 4; ++j) {
            const int cx = bn + wn*32 + j*8 + kcol;
            if (OUTM == 0) {
                float* p0 = Cf + z*zC + (long long)r0*ldc + cx;
                float* p1 = Cf + z*zC + (long long)(r0+8)*ldc + cx;
                *(float2*)p0 = make_float2(acc[i][j][0], acc[i][j][1]);
                *(float2*)p1 = make_float2(acc[i][j][2], acc[i][j][3]);
            } else {
                #pragma unroll
                for (int hrow = 0; hrow < 2; ++hrow) {
                    const float v0 = acc[i][j][hrow*2], v1 = acc[i][j][hrow*2+1];
                    const __nv_bfloat16 h0 = __float2bfloat16(v0), h1 = __float2bfloat16(v1);
                    __nv_bfloat162 hp; hp.x = h0; hp.y = h1;
                    __nv_bfloat162 lp;
                    lp.x = __float2bfloat16(v0 - __bfloat162float(h0));
                    lp.y = __float2bfloat16(v1 - __bfloat162float(h1));
                    const long long off = z*zC + (long long)(r0 + hrow*8)*ldc + cx;
                    *(__nv_bfloat162*)(Chi + off) = hp;
                    *(__nv_bfloat162*)(Clo + off) = lp;
                }
            }
        }
    }
}

// ============================================================
// Causal flash attention (fp32), epilogue writes split bf16 att.
// ============================================================
#define ASTR 68
#define ATTN_SMEM (3*64*ASTR*4)

__global__ __launch_bounds__(256) void flash_attn(
    const float* __restrict__ QKV,
    __nv_bfloat16* __restrict__ Ohi, __nv_bfloat16* __restrict__ Olo)
{
    extern __shared__ float sm[];
    float* QT = sm;
    float* KT = sm + 64*ASTR;
    float* Vs = sm + 2*64*ASTR;
    const int qb = blockIdx.x, h = blockIdx.y, b = blockIdx.z;
    const int tid = threadIdx.x;
    const int tx = tid & 15, ty = tid >> 4;
    const float scale = 0.125f;
    const long long baseQ = (long long)b*Sq*D3q + (long long)h*DHq;
    const long long baseK = baseQ + Dq;
    const long long baseV = baseQ + 2*Dq;
    const int q0 = qb*64;

    #pragma unroll
    for (int l=0;l<4;l++) {
        const int t = tid + l*256;
        const int r = t >> 4;
        const int c4 = (t & 15) << 2;
        const float4 v = *(const float4*)(QKV + baseQ + (long long)(q0+r)*D3q + c4);
        QT[(c4+0)*ASTR + r]=v.x; QT[(c4+1)*ASTR + r]=v.y;
        QT[(c4+2)*ASTR + r]=v.z; QT[(c4+3)*ASTR + r]=v.w;
    }

    float m_i[4], l_i[4], acc[4][4];
    #pragma unroll
    for (int i=0;i<4;i++) {
        m_i[i] = -1e30f; l_i[i] = 0.f;
        #pragma unroll
        for (int j=0;j<4;j++) acc[i][j]=0.f;
    }

    for (int kb = 0; kb <= qb; kb++) {
        const int k0 = kb*64;
        __syncthreads();
        #pragma unroll
        for (int l=0;l<4;l++) {
            const int t = tid + l*256;
            const int r = t >> 4;
            const int c4 = (t & 15) << 2;
            const float4 v = *(const float4*)(QKV + baseK + (long long)(k0+r)*D3q + c4);
            KT[(c4+0)*ASTR + r]=v.x; KT[(c4+1)*ASTR + r]=v.y;
            KT[(c4+2)*ASTR + r]=v.z; KT[(c4+3)*ASTR + r]=v.w;
            const float4 u = *(const float4*)(QKV + baseV + (long long)(k0+r)*D3q + c4);
            *(float4*)&Vs[r*ASTR + c4] = u;
        }
        __syncthreads();

        float s[4][4];
        #pragma unroll
        for (int i=0;i<4;i++)
            #pragma unroll
            for (int j=0;j<4;j++) s[i][j]=0.f;
        #pragma unroll 4
        for (int kk=0;kk<64;kk++) {
            const float4 av = *(const float4*)&QT[kk*ASTR + ty*4];
            const float4 bv = *(const float4*)&KT[kk*ASTR + tx*4];
            const float a0=av.x,a1=av.y,a2=av.z,a3=av.w;
            const float b0=bv.x,b1=bv.y,b2=bv.z,b3=bv.w;
            s[0][0]+=a0*b0; s[0][1]+=a0*b1; s[0][2]+=a0*b2; s[0][3]+=a0*b3;
            s[1][0]+=a1*b0; s[1][1]+=a1*b1; s[1][2]+=a1*b2; s[1][3]+=a1*b3;
            s[2][0]+=a2*b0; s[2][1]+=a2*b1; s[2][2]+=a2*b2; s[2][3]+=a2*b3;
            s[3][0]+=a3*b0; s[3][1]+=a3*b1; s[3][2]+=a3*b2; s[3][3]+=a3*b3;
        }

        const bool diag = (kb == qb);
        #pragma unroll
        for (int i=0;i<4;i++) {
            const int r = ty*4 + i;
            #pragma unroll
            for (int j=0;j<4;j++) {
                const int c = tx*4 + j;
                float v = s[i][j]*scale;
                if (diag && c > r) v = -1e30f;
                s[i][j] = v;
            }
        }

        #pragma unroll
        for (int i=0;i<4;i++) {
            float rm = fmaxf(fmaxf(s[i][0],s[i][1]), fmaxf(s[i][2],s[i][3]));
            #pragma unroll
            for (int m=1;m<16;m<<=1) rm = fmaxf(rm, __shfl_xor_sync(0xffffffffu, rm, m));
            const float mnew = fmaxf(m_i[i], rm);
            const float f = __expf(m_i[i] - mnew);
            float rs = 0.f;
            #pragma unroll
            for (int j=0;j<4;j++) { const float p = __expf(s[i][j]-mnew); s[i][j]=p; rs += p; }
            #pragma unroll
            for (int m=1;m<16;m<<=1) rs += __shfl_xor_sync(0xffffffffu, rs, m);
            l_i[i] = l_i[i]*f + rs;
            m_i[i] = mnew;
            #pragma unroll
            for (int j=0;j<4;j++) acc[i][j] *= f;
        }

        __syncthreads();
        #pragma unroll
        for (int i=0;i<4;i++)
            #pragma unroll
            for (int j=0;j<4;j++)
                KT[(tx*4+j)*ASTR + ty*4 + i] = s[i][j];
        __syncthreads();

        #pragma unroll 4
        for (int cc=0;cc<64;cc++) {
            const float4 av = *(const float4*)&KT[cc*ASTR + ty*4];
            const float4 bv = *(const float4*)&Vs[cc*ASTR + tx*4];
            const float a0=av.x,a1=av.y,a2=av.z,a3=av.w;
            const float b0=bv.x,b1=bv.y,b2=bv.z,b3=bv.w;
            acc[0][0]+=a0*b0; acc[0][1]+=a0*b1; acc[0][2]+=a0*b2; acc[0][3]+=a0*b3;
            acc[1][0]+=a1*b0; acc[1][1]+=a1*b1; acc[1][2]+=a1*b2; acc[1][3]+=a1*b3;
            acc[2][0]+=a2*b0; acc[2][1]+=a2*b1; acc[2][2]+=a2*b2; acc[2][3]+=a2*b3;
            acc[3][0]+=a3*b0; acc[3][1]+=a3*b1; acc[3][2]+=a3*b2; acc[3][3]+=a3*b3;
        }
    }

    #pragma unroll
    for (int i=0;i<4;i++) {
        const float inv = 1.0f / l_i[i];
        const int r = q0 + ty*4 + i;
        const long long off = (long long)b*Sq*Dq + (long long)r*Dq + h*DHq + tx*4;
        const float v0 = acc[i][0]*inv, v1 = acc[i][1]*inv, v2 = acc[i][2]*inv, v3 = acc[i][3]*inv;
        const __nv_bfloat16 h0=__float2bfloat16(v0), h1=__float2bfloat16(v1);
        const __nv_bfloat16 h2=__float2bfloat16(v2), h3=__float2bfloat16(v3);
        __nv_bfloat162 ha; ha.x=h0; ha.y=h1;
        __nv_bfloat162 hb; hb.x=h2; hb.y=h3;
        __nv_bfloat162 la; la.x=__float2bfloat16(v0-__bfloat162float(h0)); la.y=__float2bfloat16(v1-__bfloat162float(h1));
        __nv_bfloat162 lb; lb.x=__float2bfloat16(v2-__bfloat162float(h2)); lb.y=__float2bfloat16(v3-__bfloat162float(h3));
        *(__nv_bfloat162*)(Ohi + off)     = ha;
        *(__nv_bfloat162*)(Ohi + off + 2) = hb;
        *(__nv_bfloat162*)(Olo + off)     = la;
        *(__nv_bfloat162*)(Olo + off + 2) = lb;
    }
}

// ============================================================
// launch
// ============================================================
extern "C" void kernel_launch(void* const* d_in, const int* in_sizes, int n_in,
                              void* d_out, int out_size)
{
    const float* x       = (const float*)d_in[0];
    const float* cw      = (const float*)d_in[1];
    const int*   ci      = (const int*)  d_in[2];
    const float* wQ      = (const float*)d_in[3];
    const int*   iQ      = (const int*)  d_in[4];
    const float* wK      = (const float*)d_in[5];
    const int*   iK      = (const int*)  d_in[6];
    const float* wV      = (const float*)d_in[7];
    const int*   iV      = (const int*)  d_in[8];
    const float* neurons = (const float*)d_in[9];
    const float* pool    = (const float*)d_in[10];
    const float* WO      = (const float*)d_in[11];
    float* out = (float*)d_out;

    __nv_bfloat16 *pxhi, *pxlo, *pWcThi, *pWcTlo, *phhi, *phlo, *pWqThi, *pWqTlo, *patthi, *pattlo, *pWOhi, *pWOlo;
    float *pWc, *pWqkv, *pQKV;
    cudaGetSymbolAddress((void**)&pxhi,   g_xhi);
    cudaGetSymbolAddress((void**)&pxlo,   g_xlo);
    cudaGetSymbolAddress((void**)&pWc,    g_Wc);
    cudaGetSymbolAddress((void**)&pWcThi, g_WcThi);
    cudaGetSymbolAddress((void**)&pWcTlo, g_WcTlo);
    cudaGetSymbolAddress((void**)&phhi,   g_hhi);
    cudaGetSymbolAddress((void**)&phlo,   g_hlo);
    cudaGetSymbolAddress((void**)&pWqkv,  g_Wqkv);
    cudaGetSymbolAddress((void**)&pWqThi, g_WqThi);
    cudaGetSymbolAddress((void**)&pWqTlo, g_WqTlo);
    cudaGetSymbolAddress((void**)&pQKV,   g_QKV);
    cudaGetSymbolAddress((void**)&patthi, g_atthi);
    cudaGetSymbolAddress((void**)&pattlo, g_attlo);
    cudaGetSymbolAddress((void**)&pWOhi,  g_WOhi);
    cudaGetSymbolAddress((void**)&pWOlo,  g_WOlo);

    cudaFuncSetAttribute(gemm_hmma3<0>, cudaFuncAttributeMaxDynamicSharedMemorySize, GSMEM);
    cudaFuncSetAttribute(gemm_hmma3<1>, cudaFuncAttributeMaxDynamicSharedMemorySize, GSMEM);
    cudaFuncSetAttribute(flash_attn, cudaFuncAttributeMaxDynamicSharedMemorySize, ATTN_SMEM);

    // 0) splits of inputs
    split_fp32<<<(Bq*Sq*Dq/4)/256, 256>>>((const float4*)x, pxhi, pxlo);
    split_fp32<<<(Dq*Dq/4)/256, 256>>>((const float4*)WO, pWOhi, pWOlo);

    // 1) gather compress -> fp32 Wc [B][D][R], transpose+split -> [B][R][D]
    build_wc<<<dim3(Dq*Rq/4/256, Bq), 256>>>(cw, ci, neurons, pWc);
    transpose_split<<<dim3(Rq/32, Dq/32, Bq), dim3(32,8)>>>(
        pWc, pWcThi, pWcTlo, Dq, Rq, (long long)Dq*Rq, (long long)Rq*Dq);

    // 2) gather expand -> fp32 Wqkv [B][R][3D], transpose+split -> [B][3D][R]
    build_wqkv<<<dim3(Rq*Dq/4/256, 3, Bq), 256>>>(wQ, wK, wV, iQ, iK, iV, pool, pWqkv);
    transpose_split<<<dim3(D3q/32, Rq/32, Bq), dim3(32,8)>>>(
        pWqkv, pWqThi, pWqTlo, Rq, D3q, (long long)Rq*D3q, (long long)D3q*Rq);

    // 3) h = x @ Wc  (M=1024, N=128, K=1024, batch 8) -> split bf16 h
    gemm_hmma3<1><<<dim3(Rq/128, Sq/128, Bq), 256, GSMEM>>>(
        pxhi, pxlo, pWcThi, pWcTlo, nullptr, phhi, phlo,
        Dq, Dq, Rq, Dq, (long long)Sq*Dq, (long long)Rq*Dq, (long long)Sq*Rq);

    // 4) QKV = h @ Wqkv  (M=1024, N=3072, K=128, batch 8) -> fp32 QKV
    gemm_hmma3<0><<<dim3(D3q/128, Sq/128, Bq), 256, GSMEM>>>(
        phhi, phlo, pWqThi, pWqTlo, pQKV, nullptr, nullptr,
        Rq, Rq, D3q, Rq, (long long)Sq*Rq, (long long)D3q*Rq, (long long)Sq*D3q);

    // 5) causal flash attention -> split bf16 att
    flash_attn<<<dim3(Sq/64, Hq, Bq), 256, ATTN_SMEM>>>(pQKV, patthi, pattlo);

    // 6) out = att @ W_O^T  (M=8192, N=1024, K=1024) -> fp32 out
    gemm_hmma3<0><<<dim3(Dq/128, (Bq*Sq)/128, 1), 256, GSMEM>>>(
        patthi, pattlo, pWOhi, pWOlo, out, nullptr, nullptr,
        Dq, Dq, Dq, Dq, 0, 0, 0);
}

// round 11
// speedup vs baseline: 2.2823x; 1.6731x over previous
#include <cuda_runtime.h>
#include <cuda_bf16.h>
#include <cstdint>

// ---- problem constants ----
#define Bq   8
#define Sq   1024
#define Dq   1024
#define Hq   16
#define DHq  64
#define Rq   128
#define KCq  16
#define KEq  8
#define D3q  (3*Dq)

// ---- scratch (static device allocations; no cudaMalloc anywhere) ----
__device__ __nv_bfloat16 g_xhi [(size_t)Bq*Sq*Dq];
__device__ __nv_bfloat16 g_xlo [(size_t)Bq*Sq*Dq];
__device__ float         g_Wc  [(size_t)Bq*Dq*Rq];     // [B][D][R] fp32
__device__ __nv_bfloat16 g_WcThi[(size_t)Bq*Rq*Dq];    // [B][R][D]
__device__ __nv_bfloat16 g_WcTlo[(size_t)Bq*Rq*Dq];
__device__ __nv_bfloat16 g_hhi [(size_t)Bq*Sq*Rq];     // [B][S][R]
__device__ __nv_bfloat16 g_hlo [(size_t)Bq*Sq*Rq];
__device__ float         g_Wqkv[(size_t)Bq*Rq*D3q];    // [B][R][3D] fp32
__device__ __nv_bfloat16 g_WqThi[(size_t)Bq*D3q*Rq];   // [B][3D][R]
__device__ __nv_bfloat16 g_WqTlo[(size_t)Bq*D3q*Rq];
__device__ __nv_bfloat16 g_qkvhi[(size_t)Bq*Sq*D3q];   // [B][S][3D] bf16 hi
__device__ __nv_bfloat16 g_qkvlo[(size_t)Bq*Sq*D3q];   // lo
__device__ __nv_bfloat16 g_vthi[(size_t)Bq*Hq*DHq*Sq]; // [B*H][DH][S]
__device__ __nv_bfloat16 g_vtlo[(size_t)Bq*Hq*DHq*Sq];
__device__ __nv_bfloat16 g_atthi[(size_t)Bq*Sq*Dq];    // [B][S][D]
__device__ __nv_bfloat16 g_attlo[(size_t)Bq*Sq*Dq];
__device__ __nv_bfloat16 g_WOhi[(size_t)Dq*Dq];        // [N][K] natural
__device__ __nv_bfloat16 g_WOlo[(size_t)Dq*Dq];

// ============================================================
// helpers
// ============================================================
__device__ __forceinline__ uint32_t s2u(const void* p) {
    uint32_t a;
    asm("{ .reg .u64 t; cvta.to.shared.u64 t, %1; cvt.u32.u64 %0, t; }" : "=r"(a) : "l"(p));
    return a;
}
__device__ __forceinline__ void mma16816(float* d, const uint32_t* a, const uint32_t* b) {
    asm volatile(
        "mma.sync.aligned.m16n8k16.row.col.f32.bf16.bf16.f32 "
        "{%0,%1,%2,%3}, {%4,%5,%6,%7}, {%8,%9}, {%0,%1,%2,%3};"
        : "+f"(d[0]), "+f"(d[1]), "+f"(d[2]), "+f"(d[3])
        : "r"(a[0]), "r"(a[1]), "r"(a[2]), "r"(a[3]), "r"(b[0]), "r"(b[1]));
}
__device__ __forceinline__ void cp16(uint32_t saddr, const void* g) {
    asm volatile("cp.async.cg.shared.global [%0], [%1], 16;" :: "r"(saddr), "l"(g));
}
__device__ __forceinline__ void cpcommit() { asm volatile("cp.async.commit_group;"); }
template<int N> __device__ __forceinline__ void cpwait() {
    asm volatile("cp.async.wait_group %0;" :: "n"(N));
    __syncthreads();
}
// pack two floats into bf16x2 hi word, residual lo word
__device__ __forceinline__ uint32_t pack_hilo(float a, float b, uint32_t& lo) {
    __nv_bfloat16 ha = __float2bfloat16(a), hb = __float2bfloat16(b);
    __nv_bfloat162 H; H.x = ha; H.y = hb;
    __nv_bfloat162 L;
    L.x = __float2bfloat16(a - __bfloat162float(ha));
    L.y = __float2bfloat16(b - __bfloat162float(hb));
    lo = *(uint32_t*)&L;
    return *(uint32_t*)&H;
}

// ============================================================
// fp32 -> (hi, lo) bf16 split
// ============================================================
__global__ __launch_bounds__(256) void split_fp32(
    const float4* __restrict__ in, __nv_bfloat16* __restrict__ hi, __nv_bfloat16* __restrict__ lo)
{
    const long long i = (long long)blockIdx.x * 256 + threadIdx.x;
    const float4 v = in[i];
    __nv_bfloat16 h0 = __float2bfloat16(v.x), h1 = __float2bfloat16(v.y);
    __nv_bfloat16 h2 = __float2bfloat16(v.z), h3 = __float2bfloat16(v.w);
    __nv_bfloat162 ha; ha.x = h0; ha.y = h1;
    __nv_bfloat162 hb; hb.x = h2; hb.y = h3;
    __nv_bfloat162 la; la.x = __float2bfloat16(v.x - __bfloat162float(h0));
    la.y = __float2bfloat16(v.y - __bfloat162float(h1));
    __nv_bfloat162 lb; lb.x = __float2bfloat16(v.z - __bfloat162float(h2));
    lb.y = __float2bfloat16(v.w - __bfloat162float(h3));
    *(__nv_bfloat162*)(hi + i*4)     = ha;
    *(__nv_bfloat162*)(hi + i*4 + 2) = hb;
    *(__nv_bfloat162*)(lo + i*4)     = la;
    *(__nv_bfloat162*)(lo + i*4 + 2) = lb;
}

// ============================================================
// fp32 [Rr][Cc] -> bf16 hi/lo [Cc][Rr]  (transpose + split), batched
// ============================================================
__global__ __launch_bounds__(256) void transpose_split(
    const float* __restrict__ in, __nv_bfloat16* __restrict__ ohi, __nv_bfloat16* __restrict__ olo,
    int Rr, int Cc, long long sIn, long long sOut)
{
    __shared__ float t[32][33];
    in  += (long long)blockIdx.z * sIn;
    ohi += (long long)blockIdx.z * sOut;
    olo += (long long)blockIdx.z * sOut;
    const int x  = blockIdx.x * 32 + threadIdx.x;
    const int y0 = blockIdx.y * 32;
    #pragma unroll
    for (int j = threadIdx.y; j < 32; j += 8)
        t[j][threadIdx.x] = in[(long long)(y0 + j) * Cc + x];
    __syncthreads();
    const int r = y0 + threadIdx.x;
    #pragma unroll
    for (int j = threadIdx.y; j < 32; j += 8) {
        const int c = blockIdx.x * 32 + j;
        const float v = t[threadIdx.x][j];
        const __nv_bfloat16 hv = __float2bfloat16(v);
        ohi[(long long)c * Rr + r] = hv;
        olo[(long long)c * Rr + r] = __float2bfloat16(v - __bfloat162float(hv));
    }
}

// ============================================================
// V part of qkv hi/lo -> transposed [B*H][DH][S]
// ============================================================
__global__ __launch_bounds__(256) void transpose_v(
    const __nv_bfloat16* __restrict__ hi, const __nv_bfloat16* __restrict__ lo,
    __nv_bfloat16* __restrict__ ohi, __nv_bfloat16* __restrict__ olo)
{
    __shared__ __nv_bfloat16 th[32][34];
    __shared__ __nv_bfloat16 tl[32][34];
    const int bh = blockIdx.z, b = bh >> 4, h = bh & 15;
    const int s0 = blockIdx.x * 32, d0 = blockIdx.y * 32;
    const int tx = threadIdx.x, ty = threadIdx.y;
    const long long ib = (long long)b*Sq*D3q + 2*Dq + h*DHq;
    #pragma unroll
    for (int j = ty; j < 32; j += 8) {
        th[j][tx] = hi[ib + (long long)(s0 + j)*D3q + d0 + tx];
        tl[j][tx] = lo[ib + (long long)(s0 + j)*D3q + d0 + tx];
    }
    __syncthreads();
    const long long ob = (long long)bh*DHq*Sq;
    #pragma unroll
    for (int j = ty; j < 32; j += 8) {
        ohi[ob + (long long)(d0 + j)*Sq + s0 + tx] = th[tx][j];
        olo[ob + (long long)(d0 + j)*Sq + s0 + tx] = tl[tx][j];
    }
}

// ============================================================
// gathers
// ============================================================
__global__ __launch_bounds__(256) void build_wc(
    const float* __restrict__ cw, const int* __restrict__ ci,
    const float* __restrict__ neurons, float* __restrict__ out)
{
    const int b = blockIdx.y;
    __shared__ float sw[KCq];
    __shared__ int   si[KCq];
    if (threadIdx.x < KCq) {
        sw[threadIdx.x] = cw[b*KCq + threadIdx.x];
        si[threadIdx.x] = ci[b*KCq + threadIdx.x];
    }
    __syncthreads();
    const int i = blockIdx.x*blockDim.x + threadIdx.x;
    float4 acc = make_float4(0.f,0.f,0.f,0.f);
    #pragma unroll
    for (int k = 0; k < KCq; k++) {
        const float4 v = ((const float4*)(neurons + (long long)si[k]*Dq*Rq))[i];
        const float w = sw[k];
        acc.x += w*v.x; acc.y += w*v.y; acc.z += w*v.z; acc.w += w*v.w;
    }
    ((float4*)(out + (long long)b*Dq*Rq))[i] = acc;
}

__global__ __launch_bounds__(256) void build_wqkv(
    const float* __restrict__ wQ, const float* __restrict__ wK, const float* __restrict__ wV,
    const int* __restrict__ iQ, const int* __restrict__ iK, const int* __restrict__ iV,
    const float* __restrict__ pool, float* __restrict__ out)
{
    const int m = blockIdx.y, b = blockIdx.z;
    const float* w = (m==0) ? wQ : (m==1) ? wK : wV;
    const int*  id = (m==0) ? iQ : (m==1) ? iK : iV;
    __shared__ float sw[KEq];
    __shared__ int   si[KEq];
    if (threadIdx.x < KEq) {
        sw[threadIdx.x] = w[b*KEq + threadIdx.x];
        si[threadIdx.x] = id[b*KEq + threadIdx.x];
    }
    __syncthreads();
    const int i = blockIdx.x*blockDim.x + threadIdx.x;
    float4 acc = make_float4(0.f,0.f,0.f,0.f);
    #pragma unroll
    for (int k = 0; k < KEq; k++) {
        const float4 v = ((const float4*)(pool + (long long)si[k]*Rq*Dq))[i];
        const float wk = sw[k];
        acc.x += wk*v.x; acc.y += wk*v.y; acc.z += wk*v.z; acc.w += wk*v.w;
    }
    const int e = i*4;
    const int r = e / Dq, d = e % Dq;
    *(float4*)(out + (long long)b*Rq*D3q + (long long)r*D3q + m*Dq + d) = acc;
}

// ============================================================
// HMMA split-bf16 GEMM (unchanged from R9 passing version)
// ============================================================
#define GPAD 40
#define GMAT (128*GPAD*2)
#define GSTG (4*GMAT)
#define GSMEM (2*GSTG)

template<int OUTM>
__global__ __launch_bounds__(256) void gemm_hmma3(
    const __nv_bfloat16* __restrict__ Ahi, const __nv_bfloat16* __restrict__ Alo,
    const __nv_bfloat16* __restrict__ Bhi, const __nv_bfloat16* __restrict__ Blo,
    float* __restrict__ Cf, __nv_bfloat16* __restrict__ Chi, __nv_bfloat16* __restrict__ Clo,
    int lda, int ldb, int ldc, int K,
    long long zA, long long zB, long long zC)
{
    extern __shared__ char smem[];
    const uint32_t sb = s2u(smem);
    const int tid = threadIdx.x;
    const int wid = tid >> 5, lane = tid & 31;
    const int wm = wid >> 2, wn = wid & 3;
    const int mrow = lane >> 2;
    const int kcol = (lane & 3) * 2;
    const long long z = blockIdx.z;
    Ahi += z*zA; Alo += z*zA; Bhi += z*zB; Blo += z*zB;
    const int bm = blockIdx.y*128, bn = blockIdx.x*128;

    float acc[4][4][4];
    #pragma unroll
    for (int i=0;i<4;i++)
        #pragma unroll
        for (int j=0;j<4;j++)
            #pragma unroll
            for (int q=0;q<4;q++) acc[i][j][q]=0.f;

    const int nchunk = K / 32;

    auto load_stage = [&](int buf, int k0) {
        const uint32_t s0 = sb + buf*GSTG;
        #pragma unroll
        for (int l = 0; l < 2; ++l) {
            const int ch = tid + l*256;
            const int row = ch >> 2, cc = ch & 3;
            const uint32_t so = (uint32_t)(row*(GPAD*2) + cc*16);
            const long long ga = (long long)(bm + row)*lda + k0 + cc*8;
            const long long gb = (long long)(bn + row)*ldb + k0 + cc*8;
            cp16(s0 +          so, Ahi + ga);
            cp16(s0 + GMAT   + so, Alo + ga);
            cp16(s0 + 2*GMAT + so, Bhi + gb);
            cp16(s0 + 3*GMAT + so, Blo + gb);
        }
    };

    load_stage(0, 0);
    cpcommit();

    for (int c = 0; c < nchunk; ++c) {
        if (c + 1 < nchunk) { load_stage((c+1)&1, (c+1)*32); cpcommit(); cpwait<1>(); }
        else                { cpcommit(); cpwait<0>(); }

        const char* st = smem + (c&1)*GSTG;
        const __nv_bfloat16* sAh = (const __nv_bfloat16*)(st);
        const __nv_bfloat16* sAl = (const __nv_bfloat16*)(st + GMAT);
        const __nv_bfloat16* sBh = (const __nv_bfloat16*)(st + 2*GMAT);
        const __nv_bfloat16* sBl = (const __nv_bfloat16*)(st + 3*GMAT);

        #pragma unroll
        for (int ks = 0; ks < 32; ks += 16) {
            uint32_t ah[4][4], al[4][4], bh[4][2], bl[4][2];
            #pragma unroll
            for (int i = 0; i < 4; ++i) {
                const int r0 = wm*64 + i*16 + mrow;
                ah[i][0] = *(const uint32_t*)&sAh[ r0      *GPAD + ks + kcol];
                ah[i][1] = *(const uint32_t*)&sAh[(r0 + 8) *GPAD + ks + kcol];
                ah[i][2] = *(const uint32_t*)&sAh[ r0      *GPAD + ks + kcol + 8];
                ah[i][3] = *(const uint32_t*)&sAh[(r0 + 8) *GPAD + ks + kcol + 8];
                al[i][0] = *(const uint32_t*)&sAl[ r0      *GPAD + ks + kcol];
                al[i][1] = *(const uint32_t*)&sAl[(r0 + 8) *GPAD + ks + kcol];
                al[i][2] = *(const uint32_t*)&sAl[ r0      *GPAD + ks + kcol + 8];
                al[i][3] = *(const uint32_t*)&sAl[(r0 + 8) *GPAD + ks + kcol + 8];
            }
            #pragma unroll
            for (int j = 0; j < 4; ++j) {
                const int n0 = wn*32 + j*8 + mrow;
                bh[j][0] = *(const uint32_t*)&sBh[n0*GPAD + ks + kcol];
                bh[j][1] = *(const uint32_t*)&sBh[n0*GPAD + ks + kcol + 8];
                bl[j][0] = *(const uint32_t*)&sBl[n0*GPAD + ks + kcol];
                bl[j][1] = *(const uint32_t*)&sBl[n0*GPAD + ks + kcol + 8];
            }
            #pragma unroll
            for (int i = 0; i < 4; ++i)
                #pragma unroll
                for (int j = 0; j < 4; ++j) {
                    mma16816(acc[i][j], ah[i], bh[j]);
                    mma16816(acc[i][j], ah[i], bl[j]);
                    mma16816(acc[i][j], al[i], bh[j]);
                }
        }
        __syncthreads();
    }

    #pragma unroll
    for (int i = 0; i < 4; ++i) {
        const int r0 = bm + wm*64 + i*16 + mrow;
        #pragma unroll
        for (int j = 0; j < 4; ++j) {
            const int cx = bn + wn*32 + j*8 + kcol;
            if (OUTM == 0) {
                float* p0 = Cf + z*zC + (long long)r0*ldc + cx;
                float* p1 = Cf + z*zC + (long long)(r0+8)*ldc + cx;
                *(float2*)p0 = make_float2(acc[i][j][0], acc[i][j][1]);
                *(float2*)p1 = make_float2(acc[i][j][2], acc[i][j][3]);
            } else {
                #pragma unroll
                for (int hrow = 0; hrow < 2; ++hrow) {
                    uint32_t lo;
                    const uint32_t hi = pack_hilo(acc[i][j][hrow*2], acc[i][j][hrow*2+1], lo);
                    const long long off = z*zC + (long long)(r0 + hrow*8)*ldc + cx;
                    *(uint32_t*)(Chi + off) = hi;
                    *(uint32_t*)(Clo + off) = lo;
                }
            }
        }
    }
}

// ============================================================
// Tensor-core causal flash attention (3-term split bf16).
// CTA: 64 queries, 4 warps (16 q-rows each), 64-key tiles, DH=64.
// Q fragments held in registers for the whole CTA; P stays in registers.
// ============================================================
#define FSTR  72
#define FROWB (FSTR*2)
#define ATT_SMEM (6*64*FROWB)   // Qhi,Qlo,Khi,Klo,VThi,VTlo = 55296 B

__global__ __launch_bounds__(128) void flash_attn_mma(
    const __nv_bfloat16* __restrict__ qkvhi, const __nv_bfloat16* __restrict__ qkvlo,
    const __nv_bfloat16* __restrict__ vthi, const __nv_bfloat16* __restrict__ vtlo,
    __nv_bfloat16* __restrict__ Ohi, __nv_bfloat16* __restrict__ Olo)
{
    extern __shared__ char sm8[];
    char* pQh = sm8;
    char* pQl = sm8 + 64*FROWB;
    char* pKh = sm8 + 2*64*FROWB;
    char* pKl = sm8 + 3*64*FROWB;
    char* pVh = sm8 + 4*64*FROWB;
    char* pVl = sm8 + 5*64*FROWB;
    const uint32_t uQh = s2u(pQh), uQl = s2u(pQl);
    const uint32_t uKh = s2u(pKh), uKl = s2u(pKl);
    const uint32_t uVh = s2u(pVh), uVl = s2u(pVl);

    const int qb = blockIdx.x, h = blockIdx.y, b = blockIdx.z;
    const int tid = threadIdx.x, w = tid >> 5, lane = tid & 31;
    const int r = lane >> 2, c2 = (lane & 3)*2;
    const int q0 = qb*64;

    const long long baseQ = (long long)b*Sq*D3q + h*DHq;
    const long long baseK = baseQ + Dq;
    const long long vbase = ((long long)(b*Hq + h))*DHq*Sq;

    // stage Q hi/lo (1024 16B chunks)
    #pragma unroll
    for (int t = 0; t < 8; ++t) {
        const int id = tid + t*128;
        const int mat = id >> 9, rem = id & 511;
        const int row = rem >> 3, cc = rem & 7;
        const __nv_bfloat16* src = (mat == 0 ? qkvhi : qkvlo) + baseQ + (long long)(q0 + row)*D3q + cc*8;
        cp16((mat == 0 ? uQh : uQl) + row*FROWB + cc*16, src);
    }
    cpcommit(); cpwait<0>();

    // extract Q fragments (held all kernel)
    uint32_t qh[4][4], ql[4][4];
    #pragma unroll
    for (int kk = 0; kk < 4; ++kk) {
        const int e0 = (w*16 + r)*FSTR + kk*16 + c2;
        const int e1 = (w*16 + r + 8)*FSTR + kk*16 + c2;
        qh[kk][0] = *(const uint32_t*)(pQh + 2*e0);
        qh[kk][1] = *(const uint32_t*)(pQh + 2*e1);
        qh[kk][2] = *(const uint32_t*)(pQh + 2*(e0 + 8));
        qh[kk][3] = *(const uint32_t*)(pQh + 2*(e1 + 8));
        ql[kk][0] = *(const uint32_t*)(pQl + 2*e0);
        ql[kk][1] = *(const uint32_t*)(pQl + 2*e1);
        ql[kk][2] = *(const uint32_t*)(pQl + 2*(e0 + 8));
        ql[kk][3] = *(const uint32_t*)(pQl + 2*(e1 + 8));
    }

    float m0 = -1e30f, m1 = -1e30f, l0 = 0.f, l1 = 0.f;
    float O[8][4];
    #pragma unroll
    for (int j = 0; j < 8; ++j)
        #pragma unroll
        for (int q = 0; q < 4; ++q) O[j][q] = 0.f;

    for (int kb = 0; kb <= qb; ++kb) {
        const int k0 = kb*64;
        __syncthreads();   // all warps done with previous K/V tiles
        // stage K hi/lo + VT hi/lo (2048 chunks)
        #pragma unroll
        for (int t = 0; t < 16; ++t) {
            const int id = tid + t*128;
            const int mat = id >> 9, rem = id & 511;
            const int row = rem >> 3, cc = rem & 7;
            uint32_t dst; const __nv_bfloat16* src;
            if (mat == 0)      { dst = uKh; src = qkvhi + baseK + (long long)(k0 + row)*D3q + cc*8; }
            else if (mat == 1) { dst = uKl; src = qkvlo + baseK + (long long)(k0 + row)*D3q + cc*8; }
            else if (mat == 2) { dst = uVh; src = vthi + vbase + (long long)row*Sq + k0 + cc*8; }
            else               { dst = uVl; src = vtlo + vbase + (long long)row*Sq + k0 + cc*8; }
            cp16(dst + row*FROWB + cc*16, src);
        }
        cpcommit(); cpwait<0>();

        // S = Q K^T  (3-term split)
        float s[8][4];
        #pragma unroll
        for (int j = 0; j < 8; ++j)
            #pragma unroll
            for (int q = 0; q < 4; ++q) s[j][q] = 0.f;
        #pragma unroll
        for (int kk = 0; kk < 4; ++kk) {
            #pragma unroll
            for (int j = 0; j < 8; ++j) {
                const int e = (8*j + r)*FSTR + kk*16 + c2;
                uint32_t bh[2], bl[2];
                bh[0] = *(const uint32_t*)(pKh + 2*e);
                bh[1] = *(const uint32_t*)(pKh + 2*(e + 8));
                bl[0] = *(const uint32_t*)(pKl + 2*e);
                bl[1] = *(const uint32_t*)(pKl + 2*(e + 8));
                mma16816(s[j], qh[kk], bh);
                mma16816(s[j], ql[kk], bh);
                mma16816(s[j], qh[kk], bl);
            }
        }

        // scale + causal mask
        const bool diag = (kb == qb);
        const int rl0 = w*16 + r, rl1 = rl0 + 8;
        #pragma unroll
        for (int j = 0; j < 8; ++j) {
            const int cl = 8*j + c2;
            s[j][0] *= 0.125f; s[j][1] *= 0.125f; s[j][2] *= 0.125f; s[j][3] *= 0.125f;
            if (diag) {
                if (cl     > rl0) s[j][0] = -1e30f;
                if (cl + 1 > rl0) s[j][1] = -1e30f;
                if (cl     > rl1) s[j][2] = -1e30f;
                if (cl + 1 > rl1) s[j][3] = -1e30f;
            }
        }

        // online softmax (rows rl0 from c0/c1, rl1 from c2/c3; 4 lanes share a row)
        float mx0 = -1e30f, mx1 = -1e30f;
        #pragma unroll
        for (int j = 0; j < 8; ++j) {
            mx0 = fmaxf(mx0, fmaxf(s[j][0], s[j][1]));
            mx1 = fmaxf(mx1, fmaxf(s[j][2], s[j][3]));
        }
        mx0 = fmaxf(mx0, __shfl_xor_sync(0xffffffffu, mx0, 1));
        mx0 = fmaxf(mx0, __shfl_xor_sync(0xffffffffu, mx0, 2));
        mx1 = fmaxf(mx1, __shfl_xor_sync(0xffffffffu, mx1, 1));
        mx1 = fmaxf(mx1, __shfl_xor_sync(0xffffffffu, mx1, 2));
        const float M0 = fmaxf(m0, mx0), M1 = fmaxf(m1, mx1);
        const float f0 = __expf(m0 - M0), f1 = __expf(m1 - M1);
        float rs0 = 0.f, rs1 = 0.f;
        #pragma unroll
        for (int j = 0; j < 8; ++j) {
            s[j][0] = __expf(s[j][0] - M0); s[j][1] = __expf(s[j][1] - M0);
            s[j][2] = __expf(s[j][2] - M1); s[j][3] = __expf(s[j][3] - M1);
            rs0 += s[j][0] + s[j][1];
            rs1 += s[j][2] + s[j][3];
        }
        rs0 += __shfl_xor_sync(0xffffffffu, rs0, 1);
        rs0 += __shfl_xor_sync(0xffffffffu, rs0, 2);
        rs1 += __shfl_xor_sync(0xffffffffu, rs1, 1);
        rs1 += __shfl_xor_sync(0xffffffffu, rs1, 2);
        l0 = l0*f0 + rs0; l1 = l1*f1 + rs1;
        m0 = M0; m1 = M1;
        #pragma unroll
        for (int j = 0; j < 8; ++j) {
            O[j][0] *= f0; O[j][1] *= f0; O[j][2] *= f1; O[j][3] *= f1;
        }

        // O += P V  (P fragments built from score accumulators, hi/lo split)
        #pragma unroll
        for (int kk = 0; kk < 4; ++kk) {
            const int t0 = 2*kk, t1 = 2*kk + 1;
            uint32_t ph[4], pl[4];
            ph[0] = pack_hilo(s[t0][0], s[t0][1], pl[0]);
            ph[1] = pack_hilo(s[t0][2], s[t0][3], pl[1]);
            ph[2] = pack_hilo(s[t1][0], s[t1][1], pl[2]);
            ph[3] = pack_hilo(s[t1][2], s[t1][3], pl[3]);
            #pragma unroll
            for (int j = 0; j < 8; ++j) {
                const int e = (8*j + r)*FSTR + kk*16 + c2;
                uint32_t bh[2], bl[2];
                bh[0] = *(const uint32_t*)(pVh + 2*e);
                bh[1] = *(const uint32_t*)(pVh + 2*(e + 8));
                bl[0] = *(const uint32_t*)(pVl + 2*e);
                bl[1] = *(const uint32_t*)(pVl + 2*(e + 8));
                mma16816(O[j], ph, bh);
                mma16816(O[j], pl, bh);
                mma16816(O[j], ph, bl);
            }
        }
    }

    // epilogue: normalize, split, store [B][S][D]
    const float i0 = 1.f / l0, i1 = 1.f / l1;
    const int row0 = q0 + w*16 + r, row1 = row0 + 8;
    #pragma unroll
    for (int j = 0; j < 8; ++j) {
        const int col = h*DHq + 8*j + c2;
        uint32_t lo0, lo1;
        const uint32_t hi0 = pack_hilo(O[j][0]*i0, O[j][1]*i0, lo0);
        const uint32_t hi1 = pack_hilo(O[j][2]*i1, O[j][3]*i1, lo1);
        const long long off0 = ((long long)b*Sq + row0)*Dq + col;
        const long long off1 = ((long long)b*Sq + row1)*Dq + col;
        *(uint32_t*)(Ohi + off0) = hi0;
        *(uint32_t*)(Olo + off0) = lo0;
        *(uint32_t*)(Ohi + off1) = hi1;
        *(uint32_t*)(Olo + off1) = lo1;
    }
}

// ============================================================
// launch
// ============================================================
extern "C" void kernel_launch(void* const* d_in, const int* in_sizes, int n_in,
                              void* d_out, int out_size)
{
    const float* x       = (const float*)d_in[0];
    const float* cw      = (const float*)d_in[1];
    const int*   ci      = (const int*)  d_in[2];
    const float* wQ      = (const float*)d_in[3];
    const int*   iQ      = (const int*)  d_in[4];
    const float* wK      = (const float*)d_in[5];
    const int*   iK      = (const int*)  d_in[6];
    const float* wV      = (const float*)d_in[7];
    const int*   iV      = (const int*)  d_in[8];
    const float* neurons = (const float*)d_in[9];
    const float* pool    = (const float*)d_in[10];
    const float* WO      = (const float*)d_in[11];
    float* out = (float*)d_out;

    __nv_bfloat16 *pxhi, *pxlo, *pWcThi, *pWcTlo, *phhi, *phlo, *pWqThi, *pWqTlo;
    __nv_bfloat16 *pqkvhi, *pqkvlo, *pvthi, *pvtlo, *patthi, *pattlo, *pWOhi, *pWOlo;
    float *pWc, *pWqkv;
    cudaGetSymbolAddress((void**)&pxhi,   g_xhi);
    cudaGetSymbolAddress((void**)&pxlo,   g_xlo);
    cudaGetSymbolAddress((void**)&pWc,    g_Wc);
    cudaGetSymbolAddress((void**)&pWcThi, g_WcThi);
    cudaGetSymbolAddress((void**)&pWcTlo, g_WcTlo);
    cudaGetSymbolAddress((void**)&phhi,   g_hhi);
    cudaGetSymbolAddress((void**)&phlo,   g_hlo);
    cudaGetSymbolAddress((void**)&pWqkv,  g_Wqkv);
    cudaGetSymbolAddress((void**)&pWqThi, g_WqThi);
    cudaGetSymbolAddress((void**)&pWqTlo, g_WqTlo);
    cudaGetSymbolAddress((void**)&pqkvhi, g_qkvhi);
    cudaGetSymbolAddress((void**)&pqkvlo, g_qkvlo);
    cudaGetSymbolAddress((void**)&pvthi,  g_vthi);
    cudaGetSymbolAddress((void**)&pvtlo,  g_vtlo);
    cudaGetSymbolAddress((void**)&patthi, g_atthi);
    cudaGetSymbolAddress((void**)&pattlo, g_attlo);
    cudaGetSymbolAddress((void**)&pWOhi,  g_WOhi);
    cudaGetSymbolAddress((void**)&pWOlo,  g_WOlo);

    cudaFuncSetAttribute(gemm_hmma3<0>, cudaFuncAttributeMaxDynamicSharedMemorySize, GSMEM);
    cudaFuncSetAttribute(gemm_hmma3<1>, cudaFuncAttributeMaxDynamicSharedMemorySize, GSMEM);
    cudaFuncSetAttribute(flash_attn_mma, cudaFuncAttributeMaxDynamicSharedMemorySize, ATT_SMEM);

    // 0) splits of inputs
    split_fp32<<<(Bq*Sq*Dq/4)/256, 256>>>((const float4*)x, pxhi, pxlo);
    split_fp32<<<(Dq*Dq/4)/256, 256>>>((const float4*)WO, pWOhi, pWOlo);

    // 1) gather compress -> fp32 Wc [B][D][R], transpose+split -> [B][R][D]
    build_wc<<<dim3(Dq*Rq/4/256, Bq), 256>>>(cw, ci, neurons, pWc);
    transpose_split<<<dim3(Rq/32, Dq/32, Bq), dim3(32,8)>>>(
        pWc, pWcThi, pWcTlo, Dq, Rq, (long long)Dq*Rq, (long long)Rq*Dq);

    // 2) gather expand -> fp32 Wqkv [B][R][3D], transpose+split -> [B][3D][R]
    build_wqkv<<<dim3(Rq*Dq/4/256, 3, Bq), 256>>>(wQ, wK, wV, iQ, iK, iV, pool, pWqkv);
    transpose_split<<<dim3(D3q/32, Rq/32, Bq), dim3(32,8)>>>(
        pWqkv, pWqThi, pWqTlo, Rq, D3q, (long long)Rq*D3q, (long long)D3q*Rq);

    // 3) h = x @ Wc -> split bf16 h
    gemm_hmma3<1><<<dim3(Rq/128, Sq/128, Bq), 256, GSMEM>>>(
        pxhi, pxlo, pWcThi, pWcTlo, nullptr, phhi, phlo,
        Dq, Dq, Rq, Dq, (long long)Sq*Dq, (long long)Rq*Dq, (long long)Sq*Rq);

    // 4) QKV = h @ Wqkv -> split bf16 QKV [B][S][3D]
    gemm_hmma3<1><<<dim3(D3q/128, Sq/128, Bq), 256, GSMEM>>>(
        phhi, phlo, pWqThi, pWqTlo, nullptr, pqkvhi, pqkvlo,
        Rq, Rq, D3q, Rq, (long long)Sq*Rq, (long long)D3q*Rq, (long long)Sq*D3q);

    // 4b) transpose V part -> [B*H][DH][S] hi/lo
    transpose_v<<<dim3(Sq/32, DHq/32, Bq*Hq), dim3(32,8)>>>(pqkvhi, pqkvlo, pvthi, pvtlo);

    // 5) tensor-core causal flash attention -> split bf16 att [B][S][D]
    flash_attn_mma<<<dim3(Sq/64, Hq, Bq), 128, ATT_SMEM>>>(
        pqkvhi, pqkvlo, pvthi, pvtlo, patthi, pattlo);

    // 6) out = att @ W_O^T -> fp32 out
    gemm_hmma3<0><<<dim3(Dq/128, (Bq*Sq)/128, 1), 256, GSMEM>>>(
        patthi, pattlo, pWOhi, pWOlo, out, nullptr, nullptr,
        Dq, Dq, Dq, Dq, 0, 0, 0);
}